// round 1
// baseline (speedup 1.0000x reference)
#include <cuda_runtime.h>
#include <cuda_bf16.h>
#include <cstdint>

#define N_NODES 100000
#define N_EDGES 1600000
#define D_IN    256
#define D_OUT   128

// Scratch for support = x @ W  (51.2 MB). __device__ global: allowed (no alloc).
__device__ float g_support[(size_t)N_NODES * D_OUT];

// ---------------------------------------------------------------------------
// Kernel A: support = x @ W   (M=100000, K=256, N=128)
// BM=64, BN=128, BK=16, 256 threads, 8x4 register tile per thread.
// ---------------------------------------------------------------------------
__global__ __launch_bounds__(256) void gemm_kernel(const float* __restrict__ x,
                                                   const float* __restrict__ W) {
    __shared__ float As[16][68];   // [k][row], padded stride 68 (16B-aligned, fewer bank conflicts)
    __shared__ float Bs[16][128];  // [k][col]

    const int tid = threadIdx.x;
    const int block_row = blockIdx.x * 64;
    const int tx = tid & 31;       // 32 column groups of 4
    const int ty = tid >> 5;       // 8 row groups of 8

    // A-load mapping: each thread loads one float4 of x
    const int lr = tid >> 2;             // row within tile 0..63
    const int lk = (tid & 3) * 4;        // k offset 0,4,8,12
    // B-load mapping: each thread loads two float4 rows of W
    const int bk = tid >> 5;             // 0..7
    const int bc = (tid & 31) * 4;       // col 0..124

    float acc[8][4];
#pragma unroll
    for (int r = 0; r < 8; ++r)
#pragma unroll
        for (int c = 0; c < 4; ++c) acc[r][c] = 0.0f;

    const int grow = block_row + lr;
    const bool arow_ok = (grow < N_NODES);

    for (int k0 = 0; k0 < D_IN; k0 += 16) {
        // load A tile (transposed into As[k][row])
        float4 av = arow_ok ? *(const float4*)(x + (size_t)grow * D_IN + k0 + lk)
                            : make_float4(0.f, 0.f, 0.f, 0.f);
        As[lk + 0][lr] = av.x;
        As[lk + 1][lr] = av.y;
        As[lk + 2][lr] = av.z;
        As[lk + 3][lr] = av.w;
        // load B tile
        *(float4*)&Bs[bk][bc]     = *(const float4*)(W + (size_t)(k0 + bk) * D_OUT + bc);
        *(float4*)&Bs[bk + 8][bc] = *(const float4*)(W + (size_t)(k0 + bk + 8) * D_OUT + bc);
        __syncthreads();

#pragma unroll
        for (int kk = 0; kk < 16; ++kk) {
            float a[8], b[4];
            float4 a0 = *(const float4*)&As[kk][ty * 8];
            float4 a1 = *(const float4*)&As[kk][ty * 8 + 4];
            float4 bv = *(const float4*)&Bs[kk][tx * 4];
            a[0] = a0.x; a[1] = a0.y; a[2] = a0.z; a[3] = a0.w;
            a[4] = a1.x; a[5] = a1.y; a[6] = a1.z; a[7] = a1.w;
            b[0] = bv.x; b[1] = bv.y; b[2] = bv.z; b[3] = bv.w;
#pragma unroll
            for (int r = 0; r < 8; ++r)
#pragma unroll
                for (int c = 0; c < 4; ++c)
                    acc[r][c] = fmaf(a[r], b[c], acc[r][c]);
        }
        __syncthreads();
    }

    // epilogue: write support
#pragma unroll
    for (int r = 0; r < 8; ++r) {
        int orow = block_row + ty * 8 + r;
        if (orow < N_NODES) {
            float4 v = make_float4(acc[r][0], acc[r][1], acc[r][2], acc[r][3]);
            *(float4*)(g_support + (size_t)orow * D_OUT + tx * 4) = v;
        }
    }
}

// ---------------------------------------------------------------------------
// Kernel B: out[n][d] = b[d]  (bias broadcast init; d_out is poisoned)
// ---------------------------------------------------------------------------
__global__ __launch_bounds__(256) void bias_init_kernel(const float* __restrict__ b,
                                                        float* __restrict__ out) {
    int i = blockIdx.x * blockDim.x + threadIdx.x;   // float4 index
    if (i < N_NODES * (D_OUT / 4)) {
        float4 bv = ((const float4*)b)[i & (D_OUT / 4 - 1)];
        ((float4*)out)[i] = bv;
    }
}

// ---------------------------------------------------------------------------
// Kernel C: warp-per-edge gather + scale + vector scatter-add.
// Each lane handles 4 floats (128 / 32 lanes). red.global.add.v4.f32 (sm_90+)
// quarters the atomic op count vs scalar atomicAdd.
// ---------------------------------------------------------------------------
__global__ __launch_bounds__(256) void scatter_kernel(const int* __restrict__ esrc,
                                                      const int* __restrict__ edst,
                                                      const float* __restrict__ ew,
                                                      float* __restrict__ out) {
    const int e    = (blockIdx.x * blockDim.x + threadIdx.x) >> 5;
    const int lane = threadIdx.x & 31;
    if (e >= N_EDGES) return;

    const int   s = __ldg(&esrc[e]);
    const int   d = __ldg(&edst[e]);
    const float w = __ldg(&ew[e]);

    float4 v = *((const float4*)g_support + (size_t)s * (D_OUT / 4) + lane);
    v.x *= w; v.y *= w; v.z *= w; v.w *= w;

    float4* op = (float4*)out + (size_t)d * (D_OUT / 4) + lane;
    asm volatile("red.global.add.v4.f32 [%0], {%1, %2, %3, %4};"
                 :: "l"(op), "f"(v.x), "f"(v.y), "f"(v.z), "f"(v.w)
                 : "memory");
}

// ---------------------------------------------------------------------------
// Launch: inputs per metadata order: x, edge_src, edge_dst, edge_w, W, b
// ---------------------------------------------------------------------------
extern "C" void kernel_launch(void* const* d_in, const int* in_sizes, int n_in,
                              void* d_out, int out_size) {
    const float* x    = (const float*)d_in[0];
    const int*   esrc = (const int*)d_in[1];
    const int*   edst = (const int*)d_in[2];
    const float* ew   = (const float*)d_in[3];
    const float* W    = (const float*)d_in[4];
    const float* b    = (const float*)d_in[5];
    float* out = (float*)d_out;

    // A: GEMM into g_support
    int gemm_blocks = (N_NODES + 63) / 64;   // 1563
    gemm_kernel<<<gemm_blocks, 256>>>(x, W);

    // B: out = bias
    int init_elems  = N_NODES * (D_OUT / 4);          // 3.2M float4
    int init_blocks = (init_elems + 255) / 256;
    bias_init_kernel<<<init_blocks, 256>>>(b, out);

    // C: scatter-add (warp per edge)
    long long total_threads = (long long)N_EDGES * 32;
    int scat_blocks = (int)((total_threads + 255) / 256);  // 200000
    scatter_kernel<<<scat_blocks, 256>>>(esrc, edst, ew, out);
}